// round 5
// baseline (speedup 1.0000x reference)
#include <cuda_runtime.h>
#include <cuda_bf16.h>
#include <cstdint>

// ===================== problem constants =====================
#define NBATCH 32
#define CIN    64
#define COUT   64
#define HW     16384           // 128*128
#define TILE_P 128             // pixels per CTA (M of MMA)
#define NTILES (NBATCH * (HW / TILE_P)) // 4096

// idesc kind::f16 cg1: F32 acc(bit4), A=BF16(bit7), B=BF16(bit10), N=64 (8<<17), M=128 (8<<24)
#define MMA_IDESC 0x08100490u

// SMEM layout (dynamic)
#define SMEM_TMEM_PTR 0
#define SMEM_MBAR     8
#define SMEM_RS       16       // float[64]
#define SMEM_BT       272      // float[64]
#define SMEM_A        1024     // 128 rows x 128B = 16384
#define SMEM_B        (1024 + 16384) // 64 rows x 128B = 8192
#define SMEM_TOTAL    (SMEM_B + 8192)  // 25600 B

#define SWZ128(o) ((o) ^ (((o) >> 3) & 0x70))

// ===================== PTX helpers =====================
__device__ __forceinline__ uint32_t smem_u32(const void* p) {
    uint32_t a;
    asm("{ .reg .u64 t; cvta.to.shared.u64 t, %1; cvt.u32.u64 %0, t; }" : "=r"(a) : "l"(p));
    return a;
}

__device__ __forceinline__ uint32_t elect_one() {
    uint32_t r;
    asm volatile("{\n\t.reg .pred p;\n\telect.sync _|p, 0xFFFFFFFF;\n\tselp.b32 %0, 1, 0, p;\n\t}" : "=r"(r));
    return r;
}

#define TCGEN05_ALLOC(smem_addr, nCols) \
    asm volatile("tcgen05.alloc.cta_group::1.sync.aligned.shared::cta.b32 [%0], %1;" \
        :: "r"((uint32_t)(smem_addr)), "r"((uint32_t)(nCols)) : "memory")
#define TCGEN05_DEALLOC(tmem, nCols) \
    asm volatile("tcgen05.dealloc.cta_group::1.sync.aligned.b32 %0, %1;" :: "r"(tmem), "r"((uint32_t)(nCols)))
#define TCGEN05_RELINQUISH() \
    asm volatile("tcgen05.relinquish_alloc_permit.cta_group::1.sync.aligned;")
#define TCGEN05_COMMIT(mbar) \
    asm volatile("tcgen05.commit.cta_group::1.mbarrier::arrive::one.shared::cluster.b64 [%0];" \
        :: "r"((uint32_t)(mbar)) : "memory")
#define TCGEN05_FENCE_AFTER() \
    asm volatile("tcgen05.fence::after_thread_sync;" ::: "memory")
#define TCGEN05_WAIT_LD() \
    asm volatile("tcgen05.wait::ld.sync.aligned;" ::: "memory")
#define FENCE_PROXY_ASYNC() \
    asm volatile("fence.proxy.async.shared::cta;" ::: "memory")

#define MBARRIER_INIT(mbar, cnt) \
    asm volatile("mbarrier.init.shared.b64 [%0], %1;" :: "r"((uint32_t)(mbar)), "r"((uint32_t)(cnt)) : "memory")
#define MBARRIER_INVAL(mbar) \
    asm volatile("mbarrier.inval.shared.b64 [%0];" :: "r"((uint32_t)(mbar)) : "memory")

#define MBARRIER_WAIT_PARITY(mbar, par) do { \
    uint32_t _m = (uint32_t)(mbar); uint32_t _p = (uint32_t)(par); uint32_t _d; \
    asm volatile("{\n\t.reg .pred p;\n\t" \
        "mbarrier.try_wait.parity.acquire.cta.shared::cta.b64 p, [%1], %2;\n\t" \
        "selp.b32 %0, 1, 0, p;\n\t}" : "=r"(_d) : "r"(_m), "r"(_p) : "memory"); \
    if (!_d) { \
        asm volatile("{\n\t.reg .pred P1;\n\t" \
            "WAIT_LOOP_%=:\n\t" \
            "mbarrier.try_wait.parity.acquire.cta.shared::cta.b64 P1, [%0], %1, 0x989680;\n\t" \
            "@P1 bra.uni WAIT_DONE_%=;\n\t" \
            "bra.uni WAIT_LOOP_%=;\n\t" \
            "WAIT_DONE_%=:\n\t}" :: "r"(_m), "r"(_p) : "memory"); \
    } \
} while (0)

#define STS128(addr, r0, r1, r2, r3) \
    asm volatile("st.shared.v4.b32 [%0], {%1, %2, %3, %4};" \
        :: "r"((uint32_t)(addr)), "r"(r0), "r"(r1), "r"(r2), "r"(r3) : "memory")

#define TCGEN05_LD_32X32B_X32(r, tmem_addr) \
    asm volatile( \
        "tcgen05.ld.sync.aligned.32x32b.x32.b32 " \
        "{%0, %1, %2, %3, %4, %5, %6, %7, " \
        " %8, %9, %10, %11, %12, %13, %14, %15, " \
        " %16, %17, %18, %19, %20, %21, %22, %23, " \
        " %24, %25, %26, %27, %28, %29, %30, %31}, [%32];" \
        : "=r"((r)[0]),  "=r"((r)[1]),  "=r"((r)[2]),  "=r"((r)[3]), \
          "=r"((r)[4]),  "=r"((r)[5]),  "=r"((r)[6]),  "=r"((r)[7]), \
          "=r"((r)[8]),  "=r"((r)[9]),  "=r"((r)[10]), "=r"((r)[11]), \
          "=r"((r)[12]), "=r"((r)[13]), "=r"((r)[14]), "=r"((r)[15]), \
          "=r"((r)[16]), "=r"((r)[17]), "=r"((r)[18]), "=r"((r)[19]), \
          "=r"((r)[20]), "=r"((r)[21]), "=r"((r)[22]), "=r"((r)[23]), \
          "=r"((r)[24]), "=r"((r)[25]), "=r"((r)[26]), "=r"((r)[27]), \
          "=r"((r)[28]), "=r"((r)[29]), "=r"((r)[30]), "=r"((r)[31]) \
        : "r"(tmem_addr))

// 64-bit SMEM descriptor: SW128, Blackwell, K-major (LBO=1, SBO=64)
static constexpr uint64_t SMEM_DESC_BASE_SW128 =
    (uint64_t(2)  << 61) | (uint64_t(1) << 46) | (uint64_t(64) << 32) | (uint64_t(1) << 16);
#define MAKE_SMEM_DESC(base) (SMEM_DESC_BASE_SW128 | ((uint64_t)((base) >> 4) & 0x3FFF))

// ===================== single fused kernel =====================
__global__ __launch_bounds__(128) __cluster_dims__(1, 1, 1)
void qconv_main(const int* __restrict__ x,
                const float* __restrict__ in_s, const int* __restrict__ izp,
                const int* __restrict__ w, const float* __restrict__ ws,
                const int* __restrict__ wzp, const float* __restrict__ bias,
                const float* __restrict__ out_s, const int* __restrict__ ozp,
                float* __restrict__ out) {
#if !defined(__CUDA_ARCH__) || defined(__CUDA_ARCH_FEAT_SM103_ALL)
    // ---------- fast path: tcgen05 (sm_103a pass only) ----------
    extern __shared__ char smem[];
    uint32_t sb = smem_u32(smem);
    int tid = threadIdx.x;
    int wid = tid >> 5;

    int tile = blockIdx.x;
    int b = tile >> 7;                 // tile / 128
    int p0 = (tile & 127) * TILE_P;

    // --- TMEM alloc + mbarrier init (warp 0) ---
    if (wid == 0) {
        TCGEN05_ALLOC(sb + SMEM_TMEM_PTR, 64);
        if (elect_one()) MBARRIER_INIT(sb + SMEM_MBAR, 1);
        TCGEN05_RELINQUISH();
    }

    // --- per-cout requant constants into SMEM (threads 0..63) ---
    if (tid < COUT) {
        float os = out_s[0];
        ((float*)(smem + SMEM_RS))[tid] = in_s[0] * ws[tid] / os;
        ((float*)(smem + SMEM_BT))[tid] = bias[tid] / os;
    }

    // --- B tile: convert raw int32 weights -> bf16 SW128 K-major rows.
    //     Thread t handles row o = t>>1, half = t&1 (32 weights). L2-resident after wave 1.
    {
        int o = tid >> 1;
        int half = tid & 1;
        int zp = wzp[o];
        const int4* wsrc = (const int4*)(w + o * CIN + half * 32);
        unsigned rbase = (unsigned)(o * 128 + half * 64);
#pragma unroll
        for (int j = 0; j < 4; j++) {
            int4 v0 = wsrc[2 * j];
            int4 v1 = wsrc[2 * j + 1];
            __nv_bfloat162 h0 = __floats2bfloat162_rn((float)(v0.x - zp), (float)(v0.y - zp));
            __nv_bfloat162 h1 = __floats2bfloat162_rn((float)(v0.z - zp), (float)(v0.w - zp));
            __nv_bfloat162 h2 = __floats2bfloat162_rn((float)(v1.x - zp), (float)(v1.y - zp));
            __nv_bfloat162 h3 = __floats2bfloat162_rn((float)(v1.z - zp), (float)(v1.w - zp));
            unsigned off = SWZ128(rbase + j * 16);
            STS128(sb + SMEM_B + off, *(uint32_t*)&h0, *(uint32_t*)&h1,
                   *(uint32_t*)&h2, *(uint32_t*)&h3);
        }
    }

    // --- A tile: thread t owns pixel p=t; zero-point folded into conversion.
    //     64 coalesced LDG.32 + 8 swizzled STS.128. A = (float)(x - izp), exact in bf16.
    {
        int izpv = izp[0];
        const int* base = x + (size_t)b * CIN * HW + p0 + tid;
        uint32_t arow[32];
#pragma unroll
        for (int i = 0; i < 32; i++) {
            int v0 = base[(size_t)(2 * i) * HW] - izpv;
            int v1 = base[(size_t)(2 * i + 1) * HW] - izpv;
            __nv_bfloat162 h = __floats2bfloat162_rn((float)v0, (float)v1);
            arow[i] = *(uint32_t*)&h;
        }
#pragma unroll
        for (int j = 0; j < 8; j++) {
            unsigned off = SWZ128((unsigned)(tid * 128 + j * 16));
            STS128(sb + SMEM_A + off, arow[4 * j], arow[4 * j + 1], arow[4 * j + 2], arow[4 * j + 3]);
        }
    }

    FENCE_PROXY_ASYNC();
    __syncthreads();

    uint32_t tmem_base;
    asm volatile("ld.shared.b32 %0, [%1];" : "=r"(tmem_base) : "r"(sb + SMEM_TMEM_PTR));

    // --- MMA: D[128 pix, 64 cout] = A[128,64] * B[64,64]^T, K=64 in 4 steps ---
    if (wid == 0) {
        if (elect_one()) {
            uint64_t ad = MAKE_SMEM_DESC(sb + SMEM_A);
            uint64_t bd = MAKE_SMEM_DESC(sb + SMEM_B);
#pragma unroll
            for (int k = 0; k < 4; k++) {
                uint32_t en = (k > 0) ? 1u : 0u;
                uint64_t adk = ad + k * 2;
                uint64_t bdk = bd + k * 2;
                asm volatile(
                    "{\n\t.reg .pred p;\n\tsetp.ne.u32 p, %5, 0;\n\t"
                    "tcgen05.mma.cta_group::1.kind::f16 [%0], %1, %2, %3, {%4, %4, %4, %4}, p;\n\t}"
                    :: "r"(tmem_base), "l"(adk), "l"(bdk), "r"(MMA_IDESC), "r"(0u), "r"(en) : "memory");
            }
            TCGEN05_COMMIT(sb + SMEM_MBAR);
        }
    }

    MBARRIER_WAIT_PARITY(sb + SMEM_MBAR, 0);
    TCGEN05_FENCE_AFTER();

    // --- epilogue: requantize + store as float; D row = pixel (lane), col = cout ---
    const float* s_rs = (const float*)(smem + SMEM_RS);
    const float* s_bt = (const float*)(smem + SMEM_BT);
    float ozpf = (float)ozp[0];
    float* optr = out + (size_t)b * COUT * HW + p0 + tid;

#pragma unroll
    for (int c = 0; c < 2; c++) {
        uint32_t dr[32];
        TCGEN05_LD_32X32B_X32(dr, tmem_base + c * 32);
        TCGEN05_WAIT_LD();
#pragma unroll
        for (int j = 0; j < 32; j++) {
            int o = c * 32 + j;
            float dot = __uint_as_float(dr[j]);
            float f = fmaf(dot, s_rs[o], s_bt[o]);
            float q = rintf(f) + ozpf;
            q = fminf(fmaxf(q, 0.0f), 255.0f);
            optr[(size_t)o * HW] = q;
        }
    }

    __syncthreads();
    if (wid == 0) {
        if (elect_one()) MBARRIER_INVAL(sb + SMEM_MBAR);
        TCGEN05_DEALLOC(tmem_base, 64);
    }
#else
    // ---------- generic PTX fallback (compute_103 pass; never executed on GB300) ----------
    int tid = threadIdx.x;
    int tile = blockIdx.x;
    int b = tile >> 7;
    int p0 = (tile & 127) * TILE_P;

    int izpv = izp[0];
    const int* base = x + (size_t)b * CIN * HW + p0 + tid;
    float xr[CIN];
#pragma unroll
    for (int i = 0; i < CIN; i++) xr[i] = (float)(base[(size_t)i * HW] - izpv);

    float os = out_s[0];
    float isv = in_s[0];
    float ozpf = (float)ozp[0];
    float* optr = out + (size_t)b * COUT * HW + p0 + tid;
    for (int o = 0; o < COUT; o++) {
        int zp = wzp[o];
        float dot = 0.0f;
#pragma unroll
        for (int i = 0; i < CIN; i++) {
            float wv = __bfloat162float(__float2bfloat16_rn((float)(w[o * CIN + i] - zp)));
            dot += xr[i] * wv;
        }
        float rs = isv * ws[o] / os;
        float bt = bias[o] / os;
        float f = fmaf(dot, rs, bt);
        float q = rintf(f) + ozpf;
        q = fminf(fmaxf(q, 0.0f), 255.0f);
        optr[(size_t)o * HW] = q;
    }
#endif
}

// ===================== launch =====================
extern "C" void kernel_launch(void* const* d_in, const int* in_sizes, int n_in,
                              void* d_out, int out_size) {
    const int*   x    = (const int*)d_in[0];
    const float* in_s = (const float*)d_in[1];
    const int*   izp  = (const int*)d_in[2];
    const int*   w    = (const int*)d_in[3];
    const float* ws   = (const float*)d_in[4];
    const int*   wzp  = (const int*)d_in[5];
    const float* bias = (const float*)d_in[6];
    const float* os   = (const float*)d_in[7];
    const int*   ozp  = (const int*)d_in[8];
    float*       out  = (float*)d_out;

    qconv_main<<<NTILES, 128, SMEM_TOTAL>>>(x, in_s, izp, w, ws, wzp, bias, os, ozp, out);
}

// round 7
// speedup vs baseline: 1.2849x; 1.2849x over previous
#include <cuda_runtime.h>
#include <cuda_bf16.h>
#include <cstdint>

// ===================== problem constants =====================
#define NBATCH 32
#define CIN    64
#define COUT   64
#define HW     16384           // 128*128
#define TILE_P 128             // pixels per MMA tile (M)
#define TILES_PER_CTA 2
#define PIX_PER_CTA (TILE_P * TILES_PER_CTA)        // 256
#define NCTAS (NBATCH * HW / PIX_PER_CTA)           // 2048

// idesc kind::f16 cg1: F32 acc(bit4), A=BF16(bit7), B=BF16(bit10), N=64 (8<<17), M=128 (8<<24)
#define MMA_IDESC 0x08100490u

// SMEM layout (dynamic)
#define SMEM_TMEM_PTR 0
#define SMEM_MBAR     8
#define SMEM_RS       16       // float[64]
#define SMEM_BT       272      // float[64]
#define SMEM_A        1024     // 2 tiles x (128 rows x 128B) = 32768
#define SMEM_B        (1024 + 32768)   // 33792 (1024-aligned), 64 rows x 128B = 8192
#define SMEM_TOTAL    (SMEM_B + 8192)  // 41984 B < 48KB default

#define SWZ128(o) ((o) ^ (((o) >> 3) & 0x70))

// ===================== PTX helpers =====================
__device__ __forceinline__ uint32_t smem_u32(const void* p) {
    uint32_t a;
    asm("{ .reg .u64 t; cvta.to.shared.u64 t, %1; cvt.u32.u64 %0, t; }" : "=r"(a) : "l"(p));
    return a;
}

__device__ __forceinline__ uint32_t elect_one() {
    uint32_t r;
    asm volatile("{\n\t.reg .pred p;\n\telect.sync _|p, 0xFFFFFFFF;\n\tselp.b32 %0, 1, 0, p;\n\t}" : "=r"(r));
    return r;
}

#define TCGEN05_ALLOC(smem_addr, nCols) \
    asm volatile("tcgen05.alloc.cta_group::1.sync.aligned.shared::cta.b32 [%0], %1;" \
        :: "r"((uint32_t)(smem_addr)), "r"((uint32_t)(nCols)) : "memory")
#define TCGEN05_DEALLOC(tmem, nCols) \
    asm volatile("tcgen05.dealloc.cta_group::1.sync.aligned.b32 %0, %1;" :: "r"(tmem), "r"((uint32_t)(nCols)))
#define TCGEN05_RELINQUISH() \
    asm volatile("tcgen05.relinquish_alloc_permit.cta_group::1.sync.aligned;")
#define TCGEN05_COMMIT(mbar) \
    asm volatile("tcgen05.commit.cta_group::1.mbarrier::arrive::one.shared::cluster.b64 [%0];" \
        :: "r"((uint32_t)(mbar)) : "memory")
#define TCGEN05_FENCE_AFTER() \
    asm volatile("tcgen05.fence::after_thread_sync;" ::: "memory")
#define TCGEN05_WAIT_LD() \
    asm volatile("tcgen05.wait::ld.sync.aligned;" ::: "memory")
#define FENCE_PROXY_ASYNC() \
    asm volatile("fence.proxy.async.shared::cta;" ::: "memory")

#define MBARRIER_INIT(mbar, cnt) \
    asm volatile("mbarrier.init.shared.b64 [%0], %1;" :: "r"((uint32_t)(mbar)), "r"((uint32_t)(cnt)) : "memory")
#define MBARRIER_INVAL(mbar) \
    asm volatile("mbarrier.inval.shared.b64 [%0];" :: "r"((uint32_t)(mbar)) : "memory")

#define MBARRIER_WAIT_PARITY(mbar, par) do { \
    uint32_t _m = (uint32_t)(mbar); uint32_t _p = (uint32_t)(par); uint32_t _d; \
    asm volatile("{\n\t.reg .pred p;\n\t" \
        "mbarrier.try_wait.parity.acquire.cta.shared::cta.b64 p, [%1], %2;\n\t" \
        "selp.b32 %0, 1, 0, p;\n\t}" : "=r"(_d) : "r"(_m), "r"(_p) : "memory"); \
    if (!_d) { \
        asm volatile("{\n\t.reg .pred P1;\n\t" \
            "WAIT_LOOP_%=:\n\t" \
            "mbarrier.try_wait.parity.acquire.cta.shared::cta.b64 P1, [%0], %1, 0x989680;\n\t" \
            "@P1 bra.uni WAIT_DONE_%=;\n\t" \
            "bra.uni WAIT_LOOP_%=;\n\t" \
            "WAIT_DONE_%=:\n\t}" :: "r"(_m), "r"(_p) : "memory"); \
    } \
} while (0)

#define STS128(addr, r0, r1, r2, r3) \
    asm volatile("st.shared.v4.b32 [%0], {%1, %2, %3, %4};" \
        :: "r"((uint32_t)(addr)), "r"(r0), "r"(r1), "r"(r2), "r"(r3) : "memory")

#define TCGEN05_LD_32X32B_X32(r, tmem_addr) \
    asm volatile( \
        "tcgen05.ld.sync.aligned.32x32b.x32.b32 " \
        "{%0, %1, %2, %3, %4, %5, %6, %7, " \
        " %8, %9, %10, %11, %12, %13, %14, %15, " \
        " %16, %17, %18, %19, %20, %21, %22, %23, " \
        " %24, %25, %26, %27, %28, %29, %30, %31}, [%32];" \
        : "=r"((r)[0]),  "=r"((r)[1]),  "=r"((r)[2]),  "=r"((r)[3]), \
          "=r"((r)[4]),  "=r"((r)[5]),  "=r"((r)[6]),  "=r"((r)[7]), \
          "=r"((r)[8]),  "=r"((r)[9]),  "=r"((r)[10]), "=r"((r)[11]), \
          "=r"((r)[12]), "=r"((r)[13]), "=r"((r)[14]), "=r"((r)[15]), \
          "=r"((r)[16]), "=r"((r)[17]), "=r"((r)[18]), "=r"((r)[19]), \
          "=r"((r)[20]), "=r"((r)[21]), "=r"((r)[22]), "=r"((r)[23]), \
          "=r"((r)[24]), "=r"((r)[25]), "=r"((r)[26]), "=r"((r)[27]), \
          "=r"((r)[28]), "=r"((r)[29]), "=r"((r)[30]), "=r"((r)[31]) \
        : "r"(tmem_addr))

// 64-bit SMEM descriptor: SW128, Blackwell, K-major (LBO=1, SBO=64)
static constexpr uint64_t SMEM_DESC_BASE_SW128 =
    (uint64_t(2)  << 61) | (uint64_t(1) << 46) | (uint64_t(64) << 32) | (uint64_t(1) << 16);
#define MAKE_SMEM_DESC(base) (SMEM_DESC_BASE_SW128 | ((uint64_t)((base) >> 4) & 0x3FFF))

// ===================== single fused kernel: 256 threads, 2 tiles =====================
__global__ __launch_bounds__(256) __cluster_dims__(1, 1, 1)
void qconv_main(const int* __restrict__ x,
                const float* __restrict__ in_s, const int* __restrict__ izp,
                const int* __restrict__ w, const float* __restrict__ ws,
                const int* __restrict__ wzp, const float* __restrict__ bias,
                const float* __restrict__ out_s, const int* __restrict__ ozp,
                float* __restrict__ out) {
#if !defined(__CUDA_ARCH__) || defined(__CUDA_ARCH_FEAT_SM103_ALL)
    // ---------- fast path: tcgen05 (sm_103a pass only) ----------
    extern __shared__ char smem[];
    uint32_t sb = smem_u32(smem);
    int tid = threadIdx.x;
    int wid = tid >> 5;
    int wg  = tid >> 7;        // warp group 0/1 -> tile 0/1
    int wt  = tid & 127;       // thread within group = pixel within tile

    int cta = blockIdx.x;
    int b = cta >> 6;                       // cta / 64
    int p0 = (cta & 63) * PIX_PER_CTA;      // first pixel of tile pair

    int izpv = izp[0];                      // issue early: A conversion depends on it

    // --- TMEM alloc (128 cols: two 64-col D tiles) + mbarrier init (warp 0) ---
    if (wid == 0) {
        TCGEN05_ALLOC(sb + SMEM_TMEM_PTR, 128);
        if (elect_one()) MBARRIER_INIT(sb + SMEM_MBAR, 1);
        TCGEN05_RELINQUISH();
    }

    // --- per-cout requant constants into SMEM (threads 0..63) ---
    if (tid < COUT) {
        float os = out_s[0];
        ((float*)(smem + SMEM_RS))[tid] = in_s[0] * ws[tid] / os;
        ((float*)(smem + SMEM_BT))[tid] = bias[tid] / os;
    }

    // --- B tile: int32 w -> bf16, SW128 K-major. Thread t: row o=t>>2, quarter q=t&3 (16 wts).
    {
        int o = tid >> 2;
        int q = tid & 3;
        int zp = wzp[o];
        const int4* wsrc = (const int4*)(w + o * CIN + q * 16);
        unsigned rbase = (unsigned)(o * 128 + q * 32);
#pragma unroll
        for (int j = 0; j < 2; j++) {
            int4 v0 = wsrc[2 * j];
            int4 v1 = wsrc[2 * j + 1];
            __nv_bfloat162 h0 = __floats2bfloat162_rn((float)(v0.x - zp), (float)(v0.y - zp));
            __nv_bfloat162 h1 = __floats2bfloat162_rn((float)(v0.z - zp), (float)(v0.w - zp));
            __nv_bfloat162 h2 = __floats2bfloat162_rn((float)(v1.x - zp), (float)(v1.y - zp));
            __nv_bfloat162 h3 = __floats2bfloat162_rn((float)(v1.z - zp), (float)(v1.w - zp));
            unsigned off = SWZ128(rbase + j * 16);
            STS128(sb + SMEM_B + off, *(uint32_t*)&h0, *(uint32_t*)&h1,
                   *(uint32_t*)&h2, *(uint32_t*)&h3);
        }
    }

    // --- A tiles: wg g loads tile g; thread wt owns pixel p0 + g*128 + wt.
    //     64 coalesced LDG.32, zero-point folded: A = (float)(x - izp), exact in bf16.
    {
        const int* base = x + (size_t)b * CIN * HW + p0 + wg * TILE_P + wt;
        uint32_t arow[32];
#pragma unroll
        for (int i = 0; i < 32; i++) {
            int v0 = base[(size_t)(2 * i) * HW] - izpv;
            int v1 = base[(size_t)(2 * i + 1) * HW] - izpv;
            __nv_bfloat162 h = __floats2bfloat162_rn((float)v0, (float)v1);
            arow[i] = *(uint32_t*)&h;
        }
        uint32_t abase = sb + SMEM_A + wg * 16384;
#pragma unroll
        for (int j = 0; j < 8; j++) {
            unsigned off = SWZ128((unsigned)(wt * 128 + j * 16));
            STS128(abase + off, arow[4 * j], arow[4 * j + 1], arow[4 * j + 2], arow[4 * j + 3]);
        }
    }

    FENCE_PROXY_ASYNC();
    __syncthreads();

    uint32_t tmem_base;
    asm volatile("ld.shared.b32 %0, [%1];" : "=r"(tmem_base) : "r"(sb + SMEM_TMEM_PTR));

    // --- MMA: two tiles, D_t[128,64] = A_t[128,64] * B[64,64]^T, K=64 in 4 steps each ---
    if (wid == 0) {
        if (elect_one()) {
            uint64_t bd = MAKE_SMEM_DESC(sb + SMEM_B);
#pragma unroll
            for (int t = 0; t < TILES_PER_CTA; t++) {
                uint64_t ad = MAKE_SMEM_DESC(sb + SMEM_A + t * 16384);
                uint32_t dt = tmem_base + t * 64;
#pragma unroll
                for (int k = 0; k < 4; k++) {
                    uint32_t en = (k > 0) ? 1u : 0u;
                    uint64_t adk = ad + k * 2;
                    uint64_t bdk = bd + k * 2;
                    asm volatile(
                        "{\n\t.reg .pred p;\n\tsetp.ne.u32 p, %5, 0;\n\t"
                        "tcgen05.mma.cta_group::1.kind::f16 [%0], %1, %2, %3, {%4, %4, %4, %4}, p;\n\t}"
                        :: "r"(dt), "l"(adk), "l"(bdk), "r"(MMA_IDESC), "r"(0u), "r"(en) : "memory");
                }
            }
            TCGEN05_COMMIT(sb + SMEM_MBAR);
        }
    }

    MBARRIER_WAIT_PARITY(sb + SMEM_MBAR, 0);
    TCGEN05_FENCE_AFTER();

    // --- epilogue: wg g requantizes tile g from tmem_base + g*64; row = pixel, col = cout ---
    const float* s_rs = (const float*)(smem + SMEM_RS);
    const float* s_bt = (const float*)(smem + SMEM_BT);
    float ozpf = (float)ozp[0];
    float* optr = out + (size_t)b * COUT * HW + p0 + wg * TILE_P + wt;
    uint32_t dbase = tmem_base + wg * 64;

#pragma unroll
    for (int c = 0; c < 2; c++) {
        uint32_t dr[32];
        TCGEN05_LD_32X32B_X32(dr, dbase + c * 32);
        TCGEN05_WAIT_LD();
#pragma unroll
        for (int j = 0; j < 32; j++) {
            int o = c * 32 + j;
            float dot = __uint_as_float(dr[j]);
            float f = fmaf(dot, s_rs[o], s_bt[o]);
            float q = rintf(f) + ozpf;
            q = fminf(fmaxf(q, 0.0f), 255.0f);
            optr[(size_t)o * HW] = q;
        }
    }

    __syncthreads();
    if (wid == 0) {
        if (elect_one()) MBARRIER_INVAL(sb + SMEM_MBAR);
        TCGEN05_DEALLOC(tmem_base, 128);
    }
#else
    // ---------- generic PTX fallback (compute_103 pass; never executed on GB300) ----------
    int tid = threadIdx.x;
    int wg  = tid >> 7;
    int wt  = tid & 127;
    int cta = blockIdx.x;
    int b = cta >> 6;
    int p0 = (cta & 63) * PIX_PER_CTA;

    int izpv = izp[0];
    const int* base = x + (size_t)b * CIN * HW + p0 + wg * TILE_P + wt;
    float xr[CIN];
#pragma unroll
    for (int i = 0; i < CIN; i++) xr[i] = (float)(base[(size_t)i * HW] - izpv);

    float os = out_s[0];
    float isv = in_s[0];
    float ozpf = (float)ozp[0];
    float* optr = out + (size_t)b * COUT * HW + p0 + wg * TILE_P + wt;
    for (int o = 0; o < COUT; o++) {
        int zp = wzp[o];
        float dot = 0.0f;
#pragma unroll
        for (int i = 0; i < CIN; i++) {
            float wv = __bfloat162float(__float2bfloat16_rn((float)(w[o * CIN + i] - zp)));
            dot += xr[i] * wv;
        }
        float rs = isv * ws[o] / os;
        float bt = bias[o] / os;
        float f = fmaf(dot, rs, bt);
        float q = rintf(f) + ozpf;
        q = fminf(fmaxf(q, 0.0f), 255.0f);
        optr[(size_t)o * HW] = q;
    }
#endif
}

// ===================== launch =====================
extern "C" void kernel_launch(void* const* d_in, const int* in_sizes, int n_in,
                              void* d_out, int out_size) {
    const int*   x    = (const int*)d_in[0];
    const float* in_s = (const float*)d_in[1];
    const int*   izp  = (const int*)d_in[2];
    const int*   w    = (const int*)d_in[3];
    const float* ws   = (const float*)d_in[4];
    const int*   wzp  = (const int*)d_in[5];
    const float* bias = (const float*)d_in[6];
    const float* os   = (const float*)d_in[7];
    const int*   ozp  = (const int*)d_in[8];
    float*       out  = (float*)d_out;

    qconv_main<<<NCTAS, 256, SMEM_TOTAL>>>(x, in_s, izp, w, ws, wzp, bias, os, ozp, out);
}